// round 1
// baseline (speedup 1.0000x reference)
#include <cuda_runtime.h>
#include <math.h>

#define Bb 4
#define Nn 2048
#define Dd 768
#define Hh 12
#define DH 64
#define M_TOT (Bb*Nn)      /* 8192 */
#define BH (Bb*Hh)         /* 48   */

// ---------------- scratch (device globals; no allocs allowed) ----------------
__device__ float g_xn [(size_t)M_TOT * Dd];          // 25.2 MB
__device__ float g_qkv[(size_t)M_TOT * 3 * Dd];      // 75.5 MB
__device__ float g_q  [(size_t)BH * Nn * DH];        // 25.2 MB
__device__ float g_k  [(size_t)BH * Nn * DH];
__device__ float g_v  [(size_t)BH * Nn * DH];
__device__ float g_ao [(size_t)M_TOT * Dd];          // 25.2 MB

// ---------------- LayerNorm: one block per row of 768 ----------------
__global__ __launch_bounds__(256) void ln_kernel(const float* __restrict__ x,
                                                 const float* __restrict__ gamma,
                                                 const float* __restrict__ beta,
                                                 float* __restrict__ xn)
{
    const int row = blockIdx.x;
    const int t   = threadIdx.x;
    const float* xr = x + (size_t)row * Dd;
    float v0 = xr[t], v1 = xr[t + 256], v2 = xr[t + 512];
    float s  = v0 + v1 + v2;
    float sq = v0*v0 + v1*v1 + v2*v2;
    #pragma unroll
    for (int off = 16; off; off >>= 1) {
        s  += __shfl_xor_sync(0xffffffffu, s,  off);
        sq += __shfl_xor_sync(0xffffffffu, sq, off);
    }
    __shared__ float rs[8], rq[8];
    const int w = t >> 5, lane = t & 31;
    if (lane == 0) { rs[w] = s; rq[w] = sq; }
    __syncthreads();
    if (t == 0) {
        float S = 0.f, Q = 0.f;
        #pragma unroll
        for (int i = 0; i < 8; i++) { S += rs[i]; Q += rq[i]; }
        rs[0] = S; rq[0] = Q;
    }
    __syncthreads();
    const float mu   = rs[0] * (1.0f / 768.0f);
    const float var  = rq[0] * (1.0f / 768.0f) - mu * mu;
    const float rstd = rsqrtf(var + 1e-5f);
    float* xo = xn + (size_t)row * Dd;
    xo[t      ] = (v0 - mu) * rstd * gamma[t      ] + beta[t      ];
    xo[t + 256] = (v1 - mu) * rstd * gamma[t + 256] + beta[t + 256];
    xo[t + 512] = (v2 - mu) * rstd * gamma[t + 512] + beta[t + 512];
}

// ---------------- GEMM:  C[m,n] = sum_k A[m,k] * W[n,k]  (both K-contiguous) --
// 128x128 block tile, BK=16, 256 threads, 8x8 register microtile.
__global__ __launch_bounds__(256) void gemm_tn(const float* __restrict__ A,
                                               const float* __restrict__ W,
                                               float* __restrict__ C,
                                               int M, int Np, int K)
{
    __shared__ __align__(16) float As[16][128];
    __shared__ __align__(16) float Ws[16][128];

    const int tid = threadIdx.x;
    const int tx  = tid & 15;        // 16 -> n direction (8 cols each)
    const int ty  = tid >> 4;        // 16 -> m direction (8 rows each)
    const int bm  = blockIdx.y * 128;
    const int bn  = blockIdx.x * 128;

    float acc[8][8];
    #pragma unroll
    for (int i = 0; i < 8; i++)
        #pragma unroll
        for (int j = 0; j < 8; j++) acc[i][j] = 0.f;

    for (int k0 = 0; k0 < K; k0 += 16) {
        // load 128x16 A and W tiles (transposed into smem: [k][m]/[k][n])
        #pragma unroll
        for (int p = 0; p < 2; p++) {
            const int idx = tid + p * 256;           // 0..511
            const int row = idx >> 2;                // 0..127
            const int kq  = (idx & 3) * 4;           // 0,4,8,12
            float4 a = *(const float4*)&A[(size_t)(bm + row) * K + k0 + kq];
            As[kq + 0][row] = a.x; As[kq + 1][row] = a.y;
            As[kq + 2][row] = a.z; As[kq + 3][row] = a.w;
            float4 w = *(const float4*)&W[(size_t)(bn + row) * K + k0 + kq];
            Ws[kq + 0][row] = w.x; Ws[kq + 1][row] = w.y;
            Ws[kq + 2][row] = w.z; Ws[kq + 3][row] = w.w;
        }
        __syncthreads();
        #pragma unroll
        for (int kk = 0; kk < 16; kk++) {
            float4 a0 = *(const float4*)&As[kk][ty * 8];
            float4 a1 = *(const float4*)&As[kk][ty * 8 + 4];
            float4 b0 = *(const float4*)&Ws[kk][tx * 8];
            float4 b1 = *(const float4*)&Ws[kk][tx * 8 + 4];
            float av[8] = {a0.x,a0.y,a0.z,a0.w,a1.x,a1.y,a1.z,a1.w};
            float bv[8] = {b0.x,b0.y,b0.z,b0.w,b1.x,b1.y,b1.z,b1.w};
            #pragma unroll
            for (int i = 0; i < 8; i++)
                #pragma unroll
                for (int j = 0; j < 8; j++)
                    acc[i][j] += av[i] * bv[j];
        }
        __syncthreads();
    }

    #pragma unroll
    for (int i = 0; i < 8; i++) {
        const size_t off = (size_t)(bm + ty * 8 + i) * Np + bn + tx * 8;
        float4 c0 = make_float4(acc[i][0], acc[i][1], acc[i][2], acc[i][3]);
        float4 c1 = make_float4(acc[i][4], acc[i][5], acc[i][6], acc[i][7]);
        *(float4*)&C[off]     = c0;
        *(float4*)&C[off + 4] = c1;
    }
}

// ---------------- RoPE (2D axial) + head split/transpose ----------------
// qkv: [M_TOT][2304]; outputs Q/K/V: [BH][N][64]. Q gets the 1/sqrt(64) scale.
__global__ __launch_bounds__(256) void rope_kernel(const float* __restrict__ qkv,
                                                   const float* __restrict__ coords,
                                                   float* __restrict__ Qo,
                                                   float* __restrict__ Ko,
                                                   float* __restrict__ Vo)
{
    const int m = blockIdx.x;                 // 0..8191
    const int b = m >> 11;
    const int n = m & 2047;
    const float c0 = coords[m * 2 + 0];
    const float c1 = coords[m * 2 + 1];
    const float* src = qkv + (size_t)m * (3 * Dd);

    for (int t = threadIdx.x; t < 3 * Dd; t += 256) {
        const int which = t / Dd;             // 0=q 1=k 2=v
        const int r     = t - which * Dd;
        const int h     = r >> 6;
        const int d     = r & 63;
        float val;
        if (which == 2) {
            val = src[t];
        } else {
            const int slice = d >> 5;          // 0: coords axis0, 1: axis1
            const int dl    = d & 31;
            const int j     = dl & 15;
            const int isodd = dl >> 4;         // 0: real part, 1: imag part
            const float coord = slice ? c1 : c0;
            const float invf  = exp2f(-13.0f * (float)j * (1.0f / 16.0f)); // 8192^(-j/16)
            const float f  = coord * invf;
            const float cs = cosf(f);
            const float sn = sinf(f);
            const int   e  = which * Dd + h * 64 + slice * 32 + 2 * j;
            const float t1 = src[e];
            const float t2 = src[e + 1];
            val = isodd ? (t1 * sn + t2 * cs) : (t1 * cs - t2 * sn);
            if (which == 0) val *= 0.125f;     // fold in DIM_HEAD^-0.5
        }
        float* dst = (which == 0) ? Qo : ((which == 1) ? Ko : Vo);
        dst[((size_t)(b * Hh + h) * Nn + n) * DH + d] = val;
    }
}

// ---------------- Flash-style attention ----------------
// grid: (N/64, BH). 256 threads. Bq=Bk=64, 4x4 microtiles, P staged via smem.
#define STR 68   // smem row stride (floats): 272B rows -> 16B aligned, odd/32-coprime-ish
__global__ __launch_bounds__(256) void attn_kernel(const float* __restrict__ Q,
                                                   const float* __restrict__ K,
                                                   const float* __restrict__ V,
                                                   float* __restrict__ AO)
{
    extern __shared__ __align__(16) float sm[];
    float* Qs = sm;                    // [64][STR]  (d-major: Qs[d][m])
    float* Ks = Qs + 64 * STR;         // [64][STR]  (d-major: Ks[d][n])
    float* Vs = Ks + 64 * STR;         // [64][STR]  (k-major: Vs[k][d])
    float* Ps = Vs + 64 * STR;         // [64][STR]  (k-major: Ps[k][m])

    const int tid = threadIdx.x;
    const int tx  = tid & 15;
    const int ty  = tid >> 4;
    const int bh  = blockIdx.y;
    const int q0  = blockIdx.x * 64;
    const int b   = bh / Hh;
    const int h   = bh - b * Hh;

    const float* Qbh = Q + (size_t)bh * Nn * DH;
    const float* Kbh = K + (size_t)bh * Nn * DH;
    const float* Vbh = V + (size_t)bh * Nn * DH;

    // load Q tile, transposed into Qs[d][m]
    #pragma unroll
    for (int p = 0; p < 4; p++) {
        const int idx = tid + p * 256;        // 0..1023
        const int mr  = idx & 63;
        const int dq  = (idx >> 6) * 4;
        float4 qv = *(const float4*)&Qbh[(size_t)(q0 + mr) * DH + dq];
        Qs[(dq + 0) * STR + mr] = qv.x;
        Qs[(dq + 1) * STR + mr] = qv.y;
        Qs[(dq + 2) * STR + mr] = qv.z;
        Qs[(dq + 3) * STR + mr] = qv.w;
    }

    float o[4][4];
    float mrow[4], lrow[4];
    #pragma unroll
    for (int i = 0; i < 4; i++) {
        mrow[i] = -1e30f; lrow[i] = 0.f;
        #pragma unroll
        for (int j = 0; j < 4; j++) o[i][j] = 0.f;
    }

    for (int k0 = 0; k0 < Nn; k0 += 64) {
        __syncthreads();   // Qs ready (iter0) / prev stage2 done with Vs,Ps
        // K tile transposed into Ks[d][n]
        #pragma unroll
        for (int p = 0; p < 4; p++) {
            const int idx = tid + p * 256;
            const int nr  = idx & 63;
            const int dq  = (idx >> 6) * 4;
            float4 kv = *(const float4*)&Kbh[(size_t)(k0 + nr) * DH + dq];
            Ks[(dq + 0) * STR + nr] = kv.x;
            Ks[(dq + 1) * STR + nr] = kv.y;
            Ks[(dq + 2) * STR + nr] = kv.z;
            Ks[(dq + 3) * STR + nr] = kv.w;
        }
        // V tile row-major into Vs[k][d] (coalesced)
        #pragma unroll
        for (int p = 0; p < 4; p++) {
            const int idx = tid + p * 256;
            const int nr  = idx >> 4;
            const int dq  = (idx & 15) * 4;
            float4 vv = *(const float4*)&Vbh[(size_t)(k0 + nr) * DH + dq];
            *(float4*)&Vs[nr * STR + dq] = vv;
        }
        __syncthreads();

        // stage 1: S = Q K^T (over d)
        float s[4][4];
        #pragma unroll
        for (int i = 0; i < 4; i++)
            #pragma unroll
            for (int j = 0; j < 4; j++) s[i][j] = 0.f;
        #pragma unroll 16
        for (int kk = 0; kk < 64; kk++) {
            float4 a = *(const float4*)&Qs[kk * STR + ty * 4];
            float4 bb = *(const float4*)&Ks[kk * STR + tx * 4];
            float av[4] = {a.x, a.y, a.z, a.w};
            float bv[4] = {bb.x, bb.y, bb.z, bb.w};
            #pragma unroll
            for (int i = 0; i < 4; i++)
                #pragma unroll
                for (int j = 0; j < 4; j++)
                    s[i][j] += av[i] * bv[j];
        }

        // online softmax (row stats across the 16 tx lanes)
        #pragma unroll
        for (int i = 0; i < 4; i++) {
            float mt = fmaxf(fmaxf(s[i][0], s[i][1]), fmaxf(s[i][2], s[i][3]));
            #pragma unroll
            for (int off = 8; off; off >>= 1)
                mt = fmaxf(mt, __shfl_xor_sync(0xffffffffu, mt, off));
            const float mnew = fmaxf(mrow[i], mt);
            const float corr = __expf(mrow[i] - mnew);
            mrow[i] = mnew;
            float ls = 0.f;
            #pragma unroll
            for (int j = 0; j < 4; j++) {
                s[i][j] = __expf(s[i][j] - mnew);
                ls += s[i][j];
            }
            #pragma unroll
            for (int off = 8; off; off >>= 1)
                ls += __shfl_xor_sync(0xffffffffu, ls, off);
            lrow[i] = lrow[i] * corr + ls;
            #pragma unroll
            for (int j = 0; j < 4; j++) o[i][j] *= corr;
        }

        // stash P transposed: Ps[k][m]
        #pragma unroll
        for (int i = 0; i < 4; i++)
            #pragma unroll
            for (int j = 0; j < 4; j++)
                Ps[(tx * 4 + j) * STR + ty * 4 + i] = s[i][j];
        __syncthreads();

        // stage 2: O += P V (over k)
        #pragma unroll 16
        for (int kk = 0; kk < 64; kk++) {
            float4 a = *(const float4*)&Ps[kk * STR + ty * 4];
            float4 bb = *(const float4*)&Vs[kk * STR + tx * 4];
            float av[4] = {a.x, a.y, a.z, a.w};
            float bv[4] = {bb.x, bb.y, bb.z, bb.w};
            #pragma unroll
            for (int i = 0; i < 4; i++)
                #pragma unroll
                for (int j = 0; j < 4; j++)
                    o[i][j] += av[i] * bv[j];
        }
    }

    // normalize and write to AO [b][n][h*64+d]
    #pragma unroll
    for (int i = 0; i < 4; i++) {
        const float inv = 1.0f / lrow[i];
        float4 r = make_float4(o[i][0] * inv, o[i][1] * inv, o[i][2] * inv, o[i][3] * inv);
        *(float4*)&AO[((size_t)(b * Nn) + q0 + ty * 4 + i) * Dd + h * DH + tx * 4] = r;
    }
}

// ---------------- launch ----------------
extern "C" void kernel_launch(void* const* d_in, const int* in_sizes, int n_in,
                              void* d_out, int out_size)
{
    const float* x      = (const float*)d_in[0];
    const float* coords = (const float*)d_in[1];
    const float* gamma  = (const float*)d_in[2];
    const float* beta   = (const float*)d_in[3];
    const float* wqkv   = (const float*)d_in[4];
    const float* wout   = (const float*)d_in[5];
    float* out = (float*)d_out;

    float *xn, *qkv, *q, *k, *v, *ao;
    cudaGetSymbolAddress((void**)&xn,  g_xn);
    cudaGetSymbolAddress((void**)&qkv, g_qkv);
    cudaGetSymbolAddress((void**)&q,   g_q);
    cudaGetSymbolAddress((void**)&k,   g_k);
    cudaGetSymbolAddress((void**)&v,   g_v);
    cudaGetSymbolAddress((void**)&ao,  g_ao);

    const int attn_smem = 4 * 64 * STR * (int)sizeof(float);   // 69632 B
    cudaFuncSetAttribute(attn_kernel, cudaFuncAttributeMaxDynamicSharedMemorySize, attn_smem);

    ln_kernel<<<M_TOT, 256>>>(x, gamma, beta, xn);
    gemm_tn<<<dim3(3 * Dd / 128, M_TOT / 128), 256>>>(xn, wqkv, qkv, M_TOT, 3 * Dd, Dd);
    rope_kernel<<<M_TOT, 256>>>(qkv, coords, q, k, v);
    attn_kernel<<<dim3(Nn / 64, BH), 256, attn_smem>>>(q, k, v, ao);
    gemm_tn<<<dim3(Dd / 128, M_TOT / 128), 256>>>(ao, wout, out, M_TOT, Dd, Dd);
}

// round 3
// speedup vs baseline: 1.4443x; 1.4443x over previous
#include <cuda_runtime.h>
#include <math.h>
#include <cstdint>

#define Bb 4
#define Nn 2048
#define Dd 768
#define Hh 12
#define DH 64
#define M_TOT (Bb*Nn)      /* 8192 */
#define BH (Bb*Hh)         /* 48   */

// ---------------- scratch (device globals; no allocs allowed) ----------------
__device__ float g_xn [(size_t)M_TOT * Dd];
__device__ float g_qkv[(size_t)M_TOT * 3 * Dd];
__device__ float g_q  [(size_t)BH * Nn * DH];
__device__ float g_k  [(size_t)BH * Nn * DH];
__device__ float g_v  [(size_t)BH * Nn * DH];
__device__ float g_ao [(size_t)M_TOT * Dd];

// ======================= helpers =======================
__device__ __forceinline__ uint32_t smem_u32(const void* p) {
    uint32_t a;
    asm("{ .reg .u64 t; cvta.to.shared.u64 t, %1; cvt.u32.u64 %0, t; }" : "=r"(a) : "l"(p));
    return a;
}
__device__ __forceinline__ void cp16(uint32_t dst, const void* src) {
    asm volatile("cp.async.cg.shared.global [%0], [%1], 16;" :: "r"(dst), "l"(src) : "memory");
}
__device__ __forceinline__ uint32_t cvt_tf32(float x) {
    uint32_t r;
    asm("cvt.rna.tf32.f32 %0, %1;" : "=r"(r) : "f"(x));
    return r;
}
__device__ __forceinline__ void mma_tf32(float* c, uint32_t a0, uint32_t a1, uint32_t a2, uint32_t a3,
                                         uint32_t b0, uint32_t b1) {
    asm volatile("mma.sync.aligned.m16n8k8.row.col.f32.tf32.tf32.f32 "
                 "{%0,%1,%2,%3}, {%4,%5,%6,%7}, {%8,%9}, {%0,%1,%2,%3};"
                 : "+f"(c[0]), "+f"(c[1]), "+f"(c[2]), "+f"(c[3])
                 : "r"(a0), "r"(a1), "r"(a2), "r"(a3), "r"(b0), "r"(b1));
}

// ---------------- LayerNorm ----------------
__global__ __launch_bounds__(256) void ln_kernel(const float* __restrict__ x,
                                                 const float* __restrict__ gamma,
                                                 const float* __restrict__ beta,
                                                 float* __restrict__ xn)
{
    const int row = blockIdx.x;
    const int t   = threadIdx.x;
    const float* xr = x + (size_t)row * Dd;
    float v0 = xr[t], v1 = xr[t + 256], v2 = xr[t + 512];
    float s  = v0 + v1 + v2;
    float sq = v0*v0 + v1*v1 + v2*v2;
    #pragma unroll
    for (int off = 16; off; off >>= 1) {
        s  += __shfl_xor_sync(0xffffffffu, s,  off);
        sq += __shfl_xor_sync(0xffffffffu, sq, off);
    }
    __shared__ float rs[8], rq[8];
    const int w = t >> 5, lane = t & 31;
    if (lane == 0) { rs[w] = s; rq[w] = sq; }
    __syncthreads();
    if (t == 0) {
        float S = 0.f, Q = 0.f;
        #pragma unroll
        for (int i = 0; i < 8; i++) { S += rs[i]; Q += rq[i]; }
        rs[0] = S; rq[0] = Q;
    }
    __syncthreads();
    const float mu   = rs[0] * (1.0f / 768.0f);
    const float var  = rq[0] * (1.0f / 768.0f) - mu * mu;
    const float rstd = rsqrtf(var + 1e-5f);
    float* xo = xn + (size_t)row * Dd;
    xo[t      ] = (v0 - mu) * rstd * gamma[t      ] + beta[t      ];
    xo[t + 256] = (v1 - mu) * rstd * gamma[t + 256] + beta[t + 256];
    xo[t + 512] = (v2 - mu) * rstd * gamma[t + 512] + beta[t + 512];
}

// ---------------- mma.sync tf32 GEMM: C[m,n] = sum_k A[m,k]*W[n,k] ----------------
// 128x128 CTA tile, BK=32, 8 warps (2m x 4n), warp tile 64x32, m16n8k8 frags.
// k-permutation: logical k(j,ks,r) = 8j + 2ks + r  (A and B agree -> result exact).
#define ASTR 36                       /* padded floats per smem row (144B) */
#define TILE_F (128 * ASTR)           /* floats per tile */
__global__ __launch_bounds__(256) void gemm_mma(const float* __restrict__ A,
                                                const float* __restrict__ W,
                                                float* __restrict__ C,
                                                int Np, int K)
{
    extern __shared__ __align__(16) float sg[];   // [2 stages][A tile | B tile]
    const int tid  = threadIdx.x;
    const int lane = tid & 31;
    const int wid  = tid >> 5;
    const int wm   = wid >> 2;          // 0..1
    const int wn   = wid & 3;           // 0..3
    const int gq   = lane >> 2;         // 0..7
    const int jq   = lane & 3;          // 0..3
    const int bm   = blockIdx.y * 128;
    const int bn   = blockIdx.x * 128;

    float acc[4][4][4];
    #pragma unroll
    for (int i = 0; i < 4; i++)
        #pragma unroll
        for (int j = 0; j < 4; j++)
            #pragma unroll
            for (int q = 0; q < 4; q++) acc[i][j][q] = 0.f;

    const int nCh = K / 32;

#define LOAD_STAGE(IT, S) do {                                                \
    const float* Ab = A + (size_t)bm * K + (IT) * 32;                         \
    const float* Wb = W + (size_t)bn * K + (IT) * 32;                         \
    float* As_ = sg + (S) * (2 * TILE_F);                                     \
    float* Bs_ = As_ + TILE_F;                                                \
    _Pragma("unroll")                                                         \
    for (int p = 0; p < 4; p++) {                                             \
        const int idx = tid + p * 256;                                        \
        const int row = idx >> 3;                                             \
        const int c4  = (idx & 7) * 4;                                        \
        cp16(smem_u32(&As_[row * ASTR + c4]), &Ab[(size_t)row * K + c4]);     \
        cp16(smem_u32(&Bs_[row * ASTR + c4]), &Wb[(size_t)row * K + c4]);     \
    }                                                                         \
    asm volatile("cp.async.commit_group;" ::: "memory");                      \
} while (0)

    LOAD_STAGE(0, 0);

    for (int it = 0; it < nCh; it++) {
        const int s = it & 1;
        if (it + 1 < nCh) {
            LOAD_STAGE(it + 1, s ^ 1);
            asm volatile("cp.async.wait_group 1;" ::: "memory");
        } else {
            asm volatile("cp.async.wait_group 0;" ::: "memory");
        }
        __syncthreads();

        const float* As_ = sg + s * (2 * TILE_F);
        const float* Bs_ = As_ + TILE_F;

        #pragma unroll
        for (int half = 0; half < 2; half++) {
            // B fragments: per nf one float4 covering ks = 2*half, 2*half+1
            uint32_t bfr[4][4];
            #pragma unroll
            for (int nf = 0; nf < 4; nf++) {
                const int n = wn * 32 + nf * 8 + gq;
                float4 bv = *(const float4*)&Bs_[n * ASTR + jq * 8 + half * 4];
                bfr[nf][0] = cvt_tf32(bv.x); bfr[nf][1] = cvt_tf32(bv.y);
                bfr[nf][2] = cvt_tf32(bv.z); bfr[nf][3] = cvt_tf32(bv.w);
            }
            #pragma unroll
            for (int mf = 0; mf < 4; mf++) {
                const int m = wm * 64 + mf * 16 + gq;
                float4 a0v = *(const float4*)&As_[m * ASTR + jq * 8 + half * 4];
                float4 a1v = *(const float4*)&As_[(m + 8) * ASTR + jq * 8 + half * 4];
                uint32_t ar[8];
                ar[0] = cvt_tf32(a0v.x); ar[1] = cvt_tf32(a0v.y);
                ar[2] = cvt_tf32(a0v.z); ar[3] = cvt_tf32(a0v.w);
                ar[4] = cvt_tf32(a1v.x); ar[5] = cvt_tf32(a1v.y);
                ar[6] = cvt_tf32(a1v.z); ar[7] = cvt_tf32(a1v.w);
                #pragma unroll
                for (int kk = 0; kk < 2; kk++) {
                    #pragma unroll
                    for (int nf = 0; nf < 4; nf++) {
                        mma_tf32(acc[mf][nf],
                                 ar[2*kk], ar[4 + 2*kk], ar[2*kk + 1], ar[4 + 2*kk + 1],
                                 bfr[nf][2*kk], bfr[nf][2*kk + 1]);
                    }
                }
            }
        }
        __syncthreads();
    }

    // epilogue
    #pragma unroll
    for (int mf = 0; mf < 4; mf++) {
        const int r = bm + wm * 64 + mf * 16 + gq;
        #pragma unroll
        for (int nf = 0; nf < 4; nf++) {
            const int n0 = bn + wn * 32 + nf * 8 + 2 * jq;
            *(float2*)&C[(size_t)r * Np + n0]       = make_float2(acc[mf][nf][0], acc[mf][nf][1]);
            *(float2*)&C[(size_t)(r + 8) * Np + n0] = make_float2(acc[mf][nf][2], acc[mf][nf][3]);
        }
    }
#undef LOAD_STAGE
}

// ---------------- RoPE (2D axial) + head split ----------------
__global__ __launch_bounds__(256) void rope_kernel(const float* __restrict__ qkv,
                                                   const float* __restrict__ coords,
                                                   float* __restrict__ Qo,
                                                   float* __restrict__ Ko,
                                                   float* __restrict__ Vo)
{
    const int m = blockIdx.x;
    const int b = m >> 11;
    const int n = m & 2047;
    const float c0 = coords[m * 2 + 0];
    const float c1 = coords[m * 2 + 1];
    const float* src = qkv + (size_t)m * (3 * Dd);

    for (int t = threadIdx.x; t < 3 * Dd; t += 256) {
        const int which = t / Dd;
        const int r     = t - which * Dd;
        const int h     = r >> 6;
        const int d     = r & 63;
        float val;
        if (which == 2) {
            val = src[t];
        } else {
            const int slice = d >> 5;
            const int dl    = d & 31;
            const int j     = dl & 15;
            const int isodd = dl >> 4;
            const float coord = slice ? c1 : c0;
            const float invf  = exp2f(-13.0f * (float)j * (1.0f / 16.0f));
            const float f  = coord * invf;
            const float cs = cosf(f);
            const float sn = sinf(f);
            const int   e  = which * Dd + h * 64 + slice * 32 + 2 * j;
            const float t1 = src[e];
            const float t2 = src[e + 1];
            val = isodd ? (t1 * sn + t2 * cs) : (t1 * cs - t2 * sn);
            if (which == 0) val *= 0.125f;
        }
        float* dst = (which == 0) ? Qo : ((which == 1) ? Ko : Vo);
        dst[((size_t)(b * Hh + h) * Nn + n) * DH + d] = val;
    }
}

// ---------------- Flash-style attention: Bq=128, Bk=64, 8x4 microtile ----------------
#define QSTR 132
#define KSTR 68
__global__ __launch_bounds__(256, 2) void attn_kernel(const float* __restrict__ Q,
                                                      const float* __restrict__ K,
                                                      const float* __restrict__ V,
                                                      float* __restrict__ AO)
{
    extern __shared__ __align__(16) float sm[];
    float* Qs = sm;                       // [64][QSTR]  d-major over m=128
    float* Ks = Qs + 64 * QSTR;           // [64][KSTR]  d-major over n=64
    float* Vs = Ks + 64 * KSTR;           // [64][KSTR]  k-major over d=64
    float* Ps = Vs + 64 * KSTR;           // [64][QSTR]  k-major over m=128

    const int tid = threadIdx.x;
    const int tx  = tid & 15;
    const int ty  = tid >> 4;
    const int bh  = blockIdx.y;
    const int q0  = blockIdx.x * 128;
    const int b   = bh / Hh;
    const int h   = bh - b * Hh;

    const float* Qbh = Q + (size_t)bh * Nn * DH;
    const float* Kbh = K + (size_t)bh * Nn * DH;
    const float* Vbh = V + (size_t)bh * Nn * DH;

    #pragma unroll
    for (int p = 0; p < 8; p++) {
        const int idx = tid + p * 256;
        const int mr  = idx & 127;
        const int dq  = (idx >> 7) * 4;
        float4 qv = *(const float4*)&Qbh[(size_t)(q0 + mr) * DH + dq];
        Qs[(dq + 0) * QSTR + mr] = qv.x;
        Qs[(dq + 1) * QSTR + mr] = qv.y;
        Qs[(dq + 2) * QSTR + mr] = qv.z;
        Qs[(dq + 3) * QSTR + mr] = qv.w;
    }

    float o[8][4];
    float mrow[8], lrow[8];
    #pragma unroll
    for (int i = 0; i < 8; i++) {
        mrow[i] = -1e30f; lrow[i] = 0.f;
        #pragma unroll
        for (int j = 0; j < 4; j++) o[i][j] = 0.f;
    }

    for (int k0 = 0; k0 < Nn; k0 += 64) {
        __syncthreads();
        #pragma unroll
        for (int p = 0; p < 4; p++) {
            const int idx = tid + p * 256;
            const int nr  = idx & 63;
            const int dq  = (idx >> 6) * 4;
            float4 kv = *(const float4*)&Kbh[(size_t)(k0 + nr) * DH + dq];
            Ks[(dq + 0) * KSTR + nr] = kv.x;
            Ks[(dq + 1) * KSTR + nr] = kv.y;
            Ks[(dq + 2) * KSTR + nr] = kv.z;
            Ks[(dq + 3) * KSTR + nr] = kv.w;
        }
        #pragma unroll
        for (int p = 0; p < 4; p++) {
            const int idx = tid + p * 256;
            const int nr  = idx >> 4;
            const int dq  = (idx & 15) * 4;
            float4 vv = *(const float4*)&Vbh[(size_t)(k0 + nr) * DH + dq];
            *(float4*)&Vs[nr * KSTR + dq] = vv;
        }
        __syncthreads();

        float s[8][4];
        #pragma unroll
        for (int i = 0; i < 8; i++)
            #pragma unroll
            for (int j = 0; j < 4; j++) s[i][j] = 0.f;
        #pragma unroll 8
        for (int kk = 0; kk < 64; kk++) {
            float4 a0 = *(const float4*)&Qs[kk * QSTR + ty * 8];
            float4 a1 = *(const float4*)&Qs[kk * QSTR + ty * 8 + 4];
            float4 bb = *(const float4*)&Ks[kk * KSTR + tx * 4];
            float av[8] = {a0.x,a0.y,a0.z,a0.w,a1.x,a1.y,a1.z,a1.w};
            float bv[4] = {bb.x,bb.y,bb.z,bb.w};
            #pragma unroll
            for (int i = 0; i < 8; i++)
                #pragma unroll
                for (int j = 0; j < 4; j++)
                    s[i][j] += av[i] * bv[j];
        }

        #pragma unroll
        for (int i = 0; i < 8; i++) {
            float mt = fmaxf(fmaxf(s[i][0], s[i][1]), fmaxf(s[i][2], s[i][3]));
            #pragma unroll
            for (int off = 8; off; off >>= 1)
                mt = fmaxf(mt, __shfl_xor_sync(0xffffffffu, mt, off));
            const float mnew = fmaxf(mrow[i], mt);
            const float corr = __expf(mrow[i] - mnew);
            mrow[i] = mnew;
            float ls = 0.f;
            #pragma unroll
            for (int j = 0; j < 4; j++) {
                s[i][j] = __expf(s[i][j] - mnew);
                ls += s[i][j];
            }
            #pragma unroll
            for (int off = 8; off; off >>= 1)
                ls += __shfl_xor_sync(0xffffffffu, ls, off);
            lrow[i] = lrow[i] * corr + ls;
            #pragma unroll
            for (int j = 0; j < 4; j++) o[i][j] *= corr;
        }

        #pragma unroll
        for (int j = 0; j < 4; j++)
            #pragma unroll
            for (int i = 0; i < 8; i++)
                Ps[(tx * 4 + j) * QSTR + ty * 8 + i] = s[i][j];
        __syncthreads();

        #pragma unroll 8
        for (int kk = 0; kk < 64; kk++) {
            float4 a0 = *(const float4*)&Ps[kk * QSTR + ty * 8];
            float4 a1 = *(const float4*)&Ps[kk * QSTR + ty * 8 + 4];
            float4 bb = *(const float4*)&Vs[kk * KSTR + tx * 4];
            float av[8] = {a0.x,a0.y,a0.z,a0.w,a1.x,a1.y,a1.z,a1.w};
            float bv[4] = {bb.x,bb.y,bb.z,bb.w};
            #pragma unroll
            for (int i = 0; i < 8; i++)
                #pragma unroll
                for (int j = 0; j < 4; j++)
                    o[i][j] += av[i] * bv[j];
        }
    }

    #pragma unroll
    for (int i = 0; i < 8; i++) {
        const float inv = 1.0f / lrow[i];
        float4 r = make_float4(o[i][0] * inv, o[i][1] * inv, o[i][2] * inv, o[i][3] * inv);
        *(float4*)&AO[((size_t)(b * Nn) + q0 + ty * 8 + i) * Dd + h * DH + tx * 4] = r;
    }
}

// ---------------- launch ----------------
extern "C" void kernel_launch(void* const* d_in, const int* in_sizes, int n_in,
                              void* d_out, int out_size)
{
    const float* x      = (const float*)d_in[0];
    const float* coords = (const float*)d_in[1];
    const float* gamma  = (const float*)d_in[2];
    const float* beta   = (const float*)d_in[3];
    const float* wqkv   = (const float*)d_in[4];
    const float* wout   = (const float*)d_in[5];
    float* out = (float*)d_out;

    float *xn, *qkv, *q, *k, *v, *ao;
    cudaGetSymbolAddress((void**)&xn,  g_xn);
    cudaGetSymbolAddress((void**)&qkv, g_qkv);
    cudaGetSymbolAddress((void**)&q,   g_q);
    cudaGetSymbolAddress((void**)&k,   g_k);
    cudaGetSymbolAddress((void**)&v,   g_v);
    cudaGetSymbolAddress((void**)&ao,  g_ao);

    const int gemm_smem = 2 * 2 * TILE_F * (int)sizeof(float);    // 73728 B
    const int attn_smem = (2 * 64 * QSTR + 2 * 64 * KSTR) * 4;    // 102400 B
    cudaFuncSetAttribute(gemm_mma, cudaFuncAttributeMaxDynamicSharedMemorySize, gemm_smem);
    cudaFuncSetAttribute(attn_kernel, cudaFuncAttributeMaxDynamicSharedMemorySize, attn_smem);

    ln_kernel<<<M_TOT, 256>>>(x, gamma, beta, xn);
    gemm_mma<<<dim3(3 * Dd / 128, M_TOT / 128), 256, gemm_smem>>>(xn, wqkv, qkv, 3 * Dd, Dd);
    rope_kernel<<<M_TOT, 256>>>(qkv, coords, q, k, v);
    attn_kernel<<<dim3(Nn / 128, BH), 256, attn_smem>>>(q, k, v, ao);
    gemm_mma<<<dim3(Dd / 128, M_TOT / 128), 256, gemm_smem>>>(ao, wout, out, Dd, Dd);
}

// round 4
// speedup vs baseline: 2.5409x; 1.7592x over previous
#include <cuda_runtime.h>
#include <math.h>
#include <cstdint>

#define Bb 4
#define Nn 2048
#define Dd 768
#define Hh 12
#define DH 64
#define M_TOT (Bb*Nn)      /* 8192 */
#define BH (Bb*Hh)         /* 48   */

// ---------------- scratch (device globals; no allocs allowed) ----------------
__device__ float g_xn [(size_t)M_TOT * Dd];
__device__ float g_qkv[(size_t)M_TOT * 3 * Dd];
__device__ float g_q  [(size_t)BH * Nn * DH];
__device__ float g_k  [(size_t)BH * Nn * DH];
__device__ float g_v  [(size_t)BH * Nn * DH];
__device__ float g_ao [(size_t)M_TOT * Dd];

// ======================= helpers =======================
__device__ __forceinline__ uint32_t smem_u32(const void* p) {
    uint32_t a;
    asm("{ .reg .u64 t; cvta.to.shared.u64 t, %1; cvt.u32.u64 %0, t; }" : "=r"(a) : "l"(p));
    return a;
}
__device__ __forceinline__ void cp16(uint32_t dst, const void* src) {
    asm volatile("cp.async.cg.shared.global [%0], [%1], 16;" :: "r"(dst), "l"(src) : "memory");
}
__device__ __forceinline__ uint32_t cvt_tf32(float x) {
    uint32_t r;
    asm("cvt.rna.tf32.f32 %0, %1;" : "=r"(r) : "f"(x));
    return r;
}
__device__ __forceinline__ void mma_tf32(float* c, uint32_t a0, uint32_t a1, uint32_t a2, uint32_t a3,
                                         uint32_t b0, uint32_t b1) {
    asm volatile("mma.sync.aligned.m16n8k8.row.col.f32.tf32.tf32.f32 "
                 "{%0,%1,%2,%3}, {%4,%5,%6,%7}, {%8,%9}, {%0,%1,%2,%3};"
                 : "+f"(c[0]), "+f"(c[1]), "+f"(c[2]), "+f"(c[3])
                 : "r"(a0), "r"(a1), "r"(a2), "r"(a3), "r"(b0), "r"(b1));
}

// ---------------- LayerNorm ----------------
__global__ __launch_bounds__(256) void ln_kernel(const float* __restrict__ x,
                                                 const float* __restrict__ gamma,
                                                 const float* __restrict__ beta,
                                                 float* __restrict__ xn)
{
    const int row = blockIdx.x;
    const int t   = threadIdx.x;
    const float* xr = x + (size_t)row * Dd;
    float v0 = xr[t], v1 = xr[t + 256], v2 = xr[t + 512];
    float s  = v0 + v1 + v2;
    float sq = v0*v0 + v1*v1 + v2*v2;
    #pragma unroll
    for (int off = 16; off; off >>= 1) {
        s  += __shfl_xor_sync(0xffffffffu, s,  off);
        sq += __shfl_xor_sync(0xffffffffu, sq, off);
    }
    __shared__ float rs[8], rq[8];
    const int w = t >> 5, lane = t & 31;
    if (lane == 0) { rs[w] = s; rq[w] = sq; }
    __syncthreads();
    if (t == 0) {
        float S = 0.f, Q = 0.f;
        #pragma unroll
        for (int i = 0; i < 8; i++) { S += rs[i]; Q += rq[i]; }
        rs[0] = S; rq[0] = Q;
    }
    __syncthreads();
    const float mu   = rs[0] * (1.0f / 768.0f);
    const float var  = rq[0] * (1.0f / 768.0f) - mu * mu;
    const float rstd = rsqrtf(var + 1e-5f);
    float* xo = xn + (size_t)row * Dd;
    xo[t      ] = (v0 - mu) * rstd * gamma[t      ] + beta[t      ];
    xo[t + 256] = (v1 - mu) * rstd * gamma[t + 256] + beta[t + 256];
    xo[t + 512] = (v2 - mu) * rstd * gamma[t + 512] + beta[t + 512];
}

// ---------------- mma.sync tf32 GEMM: C[m,n] = sum_k A[m,k]*W[n,k] ----------------
#define ASTR 36
#define TILE_F (128 * ASTR)
__global__ __launch_bounds__(256) void gemm_mma(const float* __restrict__ A,
                                                const float* __restrict__ W,
                                                float* __restrict__ C,
                                                int Np, int K)
{
    extern __shared__ __align__(16) float sg[];
    const int tid  = threadIdx.x;
    const int lane = tid & 31;
    const int wid  = tid >> 5;
    const int wm   = wid >> 2;
    const int wn   = wid & 3;
    const int gq   = lane >> 2;
    const int jq   = lane & 3;
    const int bm   = blockIdx.y * 128;
    const int bn   = blockIdx.x * 128;

    float acc[4][4][4];
    #pragma unroll
    for (int i = 0; i < 4; i++)
        #pragma unroll
        for (int j = 0; j < 4; j++)
            #pragma unroll
            for (int q = 0; q < 4; q++) acc[i][j][q] = 0.f;

    const int nCh = K / 32;

#define LOAD_STAGE(IT, S) do {                                                \
    const float* Ab = A + (size_t)bm * K + (IT) * 32;                         \
    const float* Wb = W + (size_t)bn * K + (IT) * 32;                         \
    float* As_ = sg + (S) * (2 * TILE_F);                                     \
    float* Bs_ = As_ + TILE_F;                                                \
    _Pragma("unroll")                                                         \
    for (int p = 0; p < 4; p++) {                                             \
        const int idx = tid + p * 256;                                        \
        const int row = idx >> 3;                                             \
        const int c4  = (idx & 7) * 4;                                        \
        cp16(smem_u32(&As_[row * ASTR + c4]), &Ab[(size_t)row * K + c4]);     \
        cp16(smem_u32(&Bs_[row * ASTR + c4]), &Wb[(size_t)row * K + c4]);     \
    }                                                                         \
    asm volatile("cp.async.commit_group;" ::: "memory");                      \
} while (0)

    LOAD_STAGE(0, 0);

    for (int it = 0; it < nCh; it++) {
        const int s = it & 1;
        if (it + 1 < nCh) {
            LOAD_STAGE(it + 1, s ^ 1);
            asm volatile("cp.async.wait_group 1;" ::: "memory");
        } else {
            asm volatile("cp.async.wait_group 0;" ::: "memory");
        }
        __syncthreads();

        const float* As_ = sg + s * (2 * TILE_F);
        const float* Bs_ = As_ + TILE_F;

        #pragma unroll
        for (int half = 0; half < 2; half++) {
            uint32_t bfr[4][4];
            #pragma unroll
            for (int nf = 0; nf < 4; nf++) {
                const int n = wn * 32 + nf * 8 + gq;
                float4 bv = *(const float4*)&Bs_[n * ASTR + jq * 8 + half * 4];
                bfr[nf][0] = cvt_tf32(bv.x); bfr[nf][1] = cvt_tf32(bv.y);
                bfr[nf][2] = cvt_tf32(bv.z); bfr[nf][3] = cvt_tf32(bv.w);
            }
            #pragma unroll
            for (int mf = 0; mf < 4; mf++) {
                const int m = wm * 64 + mf * 16 + gq;
                float4 a0v = *(const float4*)&As_[m * ASTR + jq * 8 + half * 4];
                float4 a1v = *(const float4*)&As_[(m + 8) * ASTR + jq * 8 + half * 4];
                uint32_t ar[8];
                ar[0] = cvt_tf32(a0v.x); ar[1] = cvt_tf32(a0v.y);
                ar[2] = cvt_tf32(a0v.z); ar[3] = cvt_tf32(a0v.w);
                ar[4] = cvt_tf32(a1v.x); ar[5] = cvt_tf32(a1v.y);
                ar[6] = cvt_tf32(a1v.z); ar[7] = cvt_tf32(a1v.w);
                #pragma unroll
                for (int kk = 0; kk < 2; kk++) {
                    #pragma unroll
                    for (int nf = 0; nf < 4; nf++) {
                        mma_tf32(acc[mf][nf],
                                 ar[2*kk], ar[4 + 2*kk], ar[2*kk + 1], ar[4 + 2*kk + 1],
                                 bfr[nf][2*kk], bfr[nf][2*kk + 1]);
                    }
                }
            }
        }
        __syncthreads();
    }

    #pragma unroll
    for (int mf = 0; mf < 4; mf++) {
        const int r = bm + wm * 64 + mf * 16 + gq;
        #pragma unroll
        for (int nf = 0; nf < 4; nf++) {
            const int n0 = bn + wn * 32 + nf * 8 + 2 * jq;
            *(float2*)&C[(size_t)r * Np + n0]       = make_float2(acc[mf][nf][0], acc[mf][nf][1]);
            *(float2*)&C[(size_t)(r + 8) * Np + n0] = make_float2(acc[mf][nf][2], acc[mf][nf][3]);
        }
    }
#undef LOAD_STAGE
}

// ---------------- RoPE (2D axial) + head split ----------------
__global__ __launch_bounds__(256) void rope_kernel(const float* __restrict__ qkv,
                                                   const float* __restrict__ coords,
                                                   float* __restrict__ Qo,
                                                   float* __restrict__ Ko,
                                                   float* __restrict__ Vo)
{
    const int m = blockIdx.x;
    const int b = m >> 11;
    const int n = m & 2047;
    const float c0 = coords[m * 2 + 0];
    const float c1 = coords[m * 2 + 1];
    const float* src = qkv + (size_t)m * (3 * Dd);

    for (int t = threadIdx.x; t < 3 * Dd; t += 256) {
        const int which = t / Dd;
        const int r     = t - which * Dd;
        const int h     = r >> 6;
        const int d     = r & 63;
        float val;
        if (which == 2) {
            val = src[t];
        } else {
            const int slice = d >> 5;
            const int dl    = d & 31;
            const int j     = dl & 15;
            const int isodd = dl >> 4;
            const float coord = slice ? c1 : c0;
            const float invf  = exp2f(-13.0f * (float)j * (1.0f / 16.0f));
            const float f  = coord * invf;
            const float cs = cosf(f);
            const float sn = sinf(f);
            const int   e  = which * Dd + h * 64 + slice * 32 + 2 * j;
            const float t1 = src[e];
            const float t2 = src[e + 1];
            val = isodd ? (t1 * sn + t2 * cs) : (t1 * cs - t2 * sn);
            if (which == 0) val *= 0.125f;
        }
        float* dst = (which == 0) ? Qo : ((which == 1) ? Ko : Vo);
        dst[((size_t)(b * Hh + h) * Nn + n) * DH + d] = val;
    }
}

// ---------------- mma.sync tf32 flash attention ----------------
// Bq=128, Bk=64. 8 warps, warp w owns q-rows [16w,16w+16). All smem tiles hold
// tf32 bit patterns. P is warp-private (same rows produced & consumed).
#define FSTR 68   /* floats per smem row: 64 + 4 pad */
__global__ __launch_bounds__(256, 2) void attn_mma(const float* __restrict__ Q,
                                                   const float* __restrict__ K,
                                                   const float* __restrict__ V,
                                                   float* __restrict__ AO)
{
    extern __shared__ __align__(16) uint32_t sa[];
    uint32_t* Qs = sa;                     // [128][FSTR]
    uint32_t* Ps = Qs + 128 * FSTR;        // [128][FSTR]
    uint32_t* Ks = Ps + 128 * FSTR;        // [64][FSTR]
    uint32_t* Vt = Ks + 64 * FSTR;         // [64][FSTR]  (d-major: Vt[d][k])

    const int tid  = threadIdx.x;
    const int lane = tid & 31;
    const int wid  = tid >> 5;
    const int gq   = lane >> 2;
    const int jq   = lane & 3;
    const int m0   = wid * 16;             // warp's q-row base
    const int bh   = blockIdx.y;
    const int q0   = blockIdx.x * 128;
    const int b    = bh / Hh;
    const int h    = bh - b * Hh;

    const float* Qbh = Q + (size_t)bh * Nn * DH;
    const float* Kbh = K + (size_t)bh * Nn * DH;
    const float* Vbh = V + (size_t)bh * Nn * DH;

    // load Q tile (128x64), tf32-converted, row-major
    #pragma unroll
    for (int p = 0; p < 2; p++) {
        const int idx = tid + p * 256;     // 0..511
        const int row = idx >> 2;
        const int c4  = (idx & 3) * 16;    // 0,16,32,48
        #pragma unroll
        for (int u = 0; u < 4; u++) {
            float4 qv = *(const float4*)&Qbh[(size_t)(q0 + row) * DH + c4 + u * 4];
            uint4 w = make_uint4(cvt_tf32(qv.x), cvt_tf32(qv.y), cvt_tf32(qv.z), cvt_tf32(qv.w));
            *(uint4*)&Qs[row * FSTR + c4 + u * 4] = w;
        }
    }

    float o[8][4];
    #pragma unroll
    for (int t = 0; t < 8; t++)
        #pragma unroll
        for (int j = 0; j < 4; j++) o[t][j] = 0.f;
    float m_lo = -1e30f, m_hi = -1e30f, l_lo = 0.f, l_hi = 0.f;

    for (int k0 = 0; k0 < Nn; k0 += 64) {
        __syncthreads();
        // K tile [64][64] row-major, tf32
        {
            const int row = tid >> 2;          // 0..63
            const int c4  = (tid & 3) * 16;
            #pragma unroll
            for (int u = 0; u < 4; u++) {
                float4 kv = *(const float4*)&Kbh[(size_t)(k0 + row) * DH + c4 + u * 4];
                uint4 w = make_uint4(cvt_tf32(kv.x), cvt_tf32(kv.y), cvt_tf32(kv.z), cvt_tf32(kv.w));
                *(uint4*)&Ks[row * FSTR + c4 + u * 4] = w;
            }
        }
        // V tile transposed: Vt[d][k], tf32. thread -> k = idx&63 (bank-spread)
        #pragma unroll
        for (int p = 0; p < 4; p++) {
            const int idx = tid + p * 256;     // 0..1023
            const int kk  = idx & 63;
            const int d0  = (idx >> 6) * 4;
            float4 vv = *(const float4*)&Vbh[(size_t)(k0 + kk) * DH + d0];
            Vt[(d0 + 0) * FSTR + kk] = cvt_tf32(vv.x);
            Vt[(d0 + 1) * FSTR + kk] = cvt_tf32(vv.y);
            Vt[(d0 + 2) * FSTR + kk] = cvt_tf32(vv.z);
            Vt[(d0 + 3) * FSTR + kk] = cvt_tf32(vv.w);
        }
        __syncthreads();

        // ---- S = Q K^T : warp rows m0..m0+15, all 64 keys ----
        float s[8][4];
        #pragma unroll
        for (int t = 0; t < 8; t++)
            #pragma unroll
            for (int j = 0; j < 4; j++) s[t][j] = 0.f;

        #pragma unroll
        for (int g = 0; g < 2; g++) {
            #pragma unroll
            for (int half = 0; half < 2; half++) {
                const int kc = g * 32 + half * 4 + jq * 8;
                uint4 a0 = *(const uint4*)&Qs[(m0 + gq) * FSTR + kc];
                uint4 a1 = *(const uint4*)&Qs[(m0 + gq + 8) * FSTR + kc];
                uint32_t ar[8] = {a0.x, a0.y, a0.z, a0.w, a1.x, a1.y, a1.z, a1.w};
                #pragma unroll
                for (int t = 0; t < 8; t++) {
                    uint4 bv = *(const uint4*)&Ks[(t * 8 + gq) * FSTR + kc];
                    uint32_t bf[4] = {bv.x, bv.y, bv.z, bv.w};
                    #pragma unroll
                    for (int kk = 0; kk < 2; kk++)
                        mma_tf32(s[t], ar[2*kk], ar[4 + 2*kk], ar[2*kk + 1], ar[5 + 2*kk],
                                 bf[2*kk], bf[2*kk + 1]);
                }
            }
        }

        // ---- online softmax (rows gq -> c0,c1 ; gq+8 -> c2,c3) ----
        float smax_lo = -1e30f, smax_hi = -1e30f;
        #pragma unroll
        for (int t = 0; t < 8; t++) {
            smax_lo = fmaxf(smax_lo, fmaxf(s[t][0], s[t][1]));
            smax_hi = fmaxf(smax_hi, fmaxf(s[t][2], s[t][3]));
        }
        #pragma unroll
        for (int off = 1; off <= 2; off <<= 1) {
            smax_lo = fmaxf(smax_lo, __shfl_xor_sync(0xffffffffu, smax_lo, off));
            smax_hi = fmaxf(smax_hi, __shfl_xor_sync(0xffffffffu, smax_hi, off));
        }
        const float mn_lo = fmaxf(m_lo, smax_lo);
        const float mn_hi = fmaxf(m_hi, smax_hi);
        const float cr_lo = __expf(m_lo - mn_lo);
        const float cr_hi = __expf(m_hi - mn_hi);
        m_lo = mn_lo; m_hi = mn_hi;

        float ls_lo = 0.f, ls_hi = 0.f;
        #pragma unroll
        for (int t = 0; t < 8; t++) {
            float p0 = __expf(s[t][0] - mn_lo);
            float p1 = __expf(s[t][1] - mn_lo);
            float p2 = __expf(s[t][2] - mn_hi);
            float p3 = __expf(s[t][3] - mn_hi);
            ls_lo += p0 + p1;  ls_hi += p2 + p3;
            const int col = t * 8 + 2 * jq;
            Ps[(m0 + gq) * FSTR + col]     = cvt_tf32(p0);
            Ps[(m0 + gq) * FSTR + col + 1] = cvt_tf32(p1);
            Ps[(m0 + gq + 8) * FSTR + col]     = cvt_tf32(p2);
            Ps[(m0 + gq + 8) * FSTR + col + 1] = cvt_tf32(p3);
        }
        #pragma unroll
        for (int off = 1; off <= 2; off <<= 1) {
            ls_lo += __shfl_xor_sync(0xffffffffu, ls_lo, off);
            ls_hi += __shfl_xor_sync(0xffffffffu, ls_hi, off);
        }
        l_lo = l_lo * cr_lo + ls_lo;
        l_hi = l_hi * cr_hi + ls_hi;
        #pragma unroll
        for (int t = 0; t < 8; t++) {
            o[t][0] *= cr_lo; o[t][1] *= cr_lo;
            o[t][2] *= cr_hi; o[t][3] *= cr_hi;
        }
        __syncwarp();

        // ---- O += P V : A = P (warp-private rows), B = Vt[d][k] ----
        #pragma unroll
        for (int g = 0; g < 2; g++) {
            #pragma unroll
            for (int half = 0; half < 2; half++) {
                const int kc = g * 32 + half * 4 + jq * 8;
                uint4 a0 = *(const uint4*)&Ps[(m0 + gq) * FSTR + kc];
                uint4 a1 = *(const uint4*)&Ps[(m0 + gq + 8) * FSTR + kc];
                uint32_t ar[8] = {a0.x, a0.y, a0.z, a0.w, a1.x, a1.y, a1.z, a1.w};
                #pragma unroll
                for (int t = 0; t < 8; t++) {
                    uint4 bv = *(const uint4*)&Vt[(t * 8 + gq) * FSTR + kc];
                    uint32_t bf[4] = {bv.x, bv.y, bv.z, bv.w};
                    #pragma unroll
                    for (int kk = 0; kk < 2; kk++)
                        mma_tf32(o[t], ar[2*kk], ar[4 + 2*kk], ar[2*kk + 1], ar[5 + 2*kk],
                                 bf[2*kk], bf[2*kk + 1]);
                }
            }
        }
    }

    // epilogue: normalize, write AO[b][n][h*64+d]
    const float inv_lo = 1.0f / l_lo;
    const float inv_hi = 1.0f / l_hi;
    #pragma unroll
    for (int t = 0; t < 8; t++) {
        const int col = h * DH + t * 8 + 2 * jq;
        const size_t r0 = (size_t)(b * Nn + q0 + m0 + gq) * Dd + col;
        const size_t r1 = (size_t)(b * Nn + q0 + m0 + gq + 8) * Dd + col;
        *(float2*)&AO[r0] = make_float2(o[t][0] * inv_lo, o[t][1] * inv_lo);
        *(float2*)&AO[r1] = make_float2(o[t][2] * inv_hi, o[t][3] * inv_hi);
    }
}

// ---------------- launch ----------------
extern "C" void kernel_launch(void* const* d_in, const int* in_sizes, int n_in,
                              void* d_out, int out_size)
{
    const float* x      = (const float*)d_in[0];
    const float* coords = (const float*)d_in[1];
    const float* gamma  = (const float*)d_in[2];
    const float* beta   = (const float*)d_in[3];
    const float* wqkv   = (const float*)d_in[4];
    const float* wout   = (const float*)d_in[5];
    float* out = (float*)d_out;

    float *xn, *qkv, *q, *k, *v, *ao;
    cudaGetSymbolAddress((void**)&xn,  g_xn);
    cudaGetSymbolAddress((void**)&qkv, g_qkv);
    cudaGetSymbolAddress((void**)&q,   g_q);
    cudaGetSymbolAddress((void**)&k,   g_k);
    cudaGetSymbolAddress((void**)&v,   g_v);
    cudaGetSymbolAddress((void**)&ao,  g_ao);

    const int gemm_smem = 2 * 2 * TILE_F * (int)sizeof(float);          // 73728 B
    const int attn_smem = (2 * 128 * FSTR + 2 * 64 * FSTR) * 4;         // 104448 B
    cudaFuncSetAttribute(gemm_mma, cudaFuncAttributeMaxDynamicSharedMemorySize, gemm_smem);
    cudaFuncSetAttribute(attn_mma, cudaFuncAttributeMaxDynamicSharedMemorySize, attn_smem);

    ln_kernel<<<M_TOT, 256>>>(x, gamma, beta, xn);
    gemm_mma<<<dim3(3 * Dd / 128, M_TOT / 128), 256, gemm_smem>>>(xn, wqkv, qkv, 3 * Dd, Dd);
    rope_kernel<<<M_TOT, 256>>>(qkv, coords, q, k, v);
    attn_mma<<<dim3(Nn / 128, BH), 256, attn_smem>>>(q, k, v, ao);
    gemm_mma<<<dim3(Dd / 128, M_TOT / 128), 256, gemm_smem>>>(ao, wout, out, Dd, Dd);
}

// round 5
// speedup vs baseline: 2.6976x; 1.0617x over previous
#include <cuda_runtime.h>
#include <math.h>
#include <cstdint>

#define Bb 4
#define Nn 2048
#define Dd 768
#define Hh 12
#define DH 64
#define M_TOT (Bb*Nn)      /* 8192 */
#define BH (Bb*Hh)         /* 48   */

// ---------------- scratch (device globals; no allocs allowed) ----------------
__device__ float g_xn  [(size_t)M_TOT * Dd];
__device__ float g_qkv [(size_t)M_TOT * 3 * Dd];
__device__ float g_q   [(size_t)BH * Nn * DH];
__device__ float g_k   [(size_t)BH * Nn * DH];
__device__ float g_v   [(size_t)BH * Nn * DH];
__device__ float g_ao  [(size_t)M_TOT * Dd];
__device__ float g_wq  [(size_t)3 * Dd * Dd];   // tf32-rounded w_qkv
__device__ float g_wo  [(size_t)Dd * Dd];       // tf32-rounded w_out

// ======================= helpers =======================
__device__ __forceinline__ uint32_t smem_u32(const void* p) {
    uint32_t a;
    asm("{ .reg .u64 t; cvta.to.shared.u64 t, %1; cvt.u32.u64 %0, t; }" : "=r"(a) : "l"(p));
    return a;
}
__device__ __forceinline__ void cp16(uint32_t dst, const void* src) {
    asm volatile("cp.async.cg.shared.global [%0], [%1], 16;" :: "r"(dst), "l"(src) : "memory");
}
__device__ __forceinline__ uint32_t cvt_tf32(float x) {
    uint32_t r;
    asm("cvt.rna.tf32.f32 %0, %1;" : "=r"(r) : "f"(x));
    return r;
}
__device__ __forceinline__ float rnd_tf32(float x) {
    return __uint_as_float(cvt_tf32(x));
}
__device__ __forceinline__ void mma_tf32(float* c, uint32_t a0, uint32_t a1, uint32_t a2, uint32_t a3,
                                         uint32_t b0, uint32_t b1) {
    asm volatile("mma.sync.aligned.m16n8k8.row.col.f32.tf32.tf32.f32 "
                 "{%0,%1,%2,%3}, {%4,%5,%6,%7}, {%8,%9}, {%0,%1,%2,%3};"
                 : "+f"(c[0]), "+f"(c[1]), "+f"(c[2]), "+f"(c[3])
                 : "r"(a0), "r"(a1), "r"(a2), "r"(a3), "r"(b0), "r"(b1));
}

// ---------------- tf32 rounding pass (weights) ----------------
__global__ __launch_bounds__(256) void cvtw_kernel(const float* __restrict__ src,
                                                   float* __restrict__ dst, int n)
{
    const int i = (blockIdx.x * 256 + threadIdx.x) * 4;
    if (i < n) {
        float4 v = *(const float4*)&src[i];
        v.x = rnd_tf32(v.x); v.y = rnd_tf32(v.y);
        v.z = rnd_tf32(v.z); v.w = rnd_tf32(v.w);
        *(float4*)&dst[i] = v;
    }
}

// ---------------- LayerNorm (writes tf32-rounded) ----------------
__global__ __launch_bounds__(256) void ln_kernel(const float* __restrict__ x,
                                                 const float* __restrict__ gamma,
                                                 const float* __restrict__ beta,
                                                 float* __restrict__ xn)
{
    const int row = blockIdx.x;
    const int t   = threadIdx.x;
    const float* xr = x + (size_t)row * Dd;
    float v0 = xr[t], v1 = xr[t + 256], v2 = xr[t + 512];
    float s  = v0 + v1 + v2;
    float sq = v0*v0 + v1*v1 + v2*v2;
    #pragma unroll
    for (int off = 16; off; off >>= 1) {
        s  += __shfl_xor_sync(0xffffffffu, s,  off);
        sq += __shfl_xor_sync(0xffffffffu, sq, off);
    }
    __shared__ float rs[8], rq[8];
    const int w = t >> 5, lane = t & 31;
    if (lane == 0) { rs[w] = s; rq[w] = sq; }
    __syncthreads();
    if (t == 0) {
        float S = 0.f, Q = 0.f;
        #pragma unroll
        for (int i = 0; i < 8; i++) { S += rs[i]; Q += rq[i]; }
        rs[0] = S; rq[0] = Q;
    }
    __syncthreads();
    const float mu   = rs[0] * (1.0f / 768.0f);
    const float var  = rq[0] * (1.0f / 768.0f) - mu * mu;
    const float rstd = rsqrtf(var + 1e-5f);
    float* xo = xn + (size_t)row * Dd;
    xo[t      ] = rnd_tf32((v0 - mu) * rstd * gamma[t      ] + beta[t      ]);
    xo[t + 256] = rnd_tf32((v1 - mu) * rstd * gamma[t + 256] + beta[t + 256]);
    xo[t + 512] = rnd_tf32((v2 - mu) * rstd * gamma[t + 512] + beta[t + 512]);
}

// ---------------- mma.sync tf32 GEMM (operands pre-rounded; no cvt) ----------------
#define ASTR 36
#define TILE_F (128 * ASTR)
__global__ __launch_bounds__(256) void gemm_mma(const float* __restrict__ A,
                                                const float* __restrict__ W,
                                                float* __restrict__ C,
                                                int Np, int K)
{
    extern __shared__ __align__(16) float sg[];
    const int tid  = threadIdx.x;
    const int lane = tid & 31;
    const int wid  = tid >> 5;
    const int wm   = wid >> 2;
    const int wn   = wid & 3;
    const int gq   = lane >> 2;
    const int jq   = lane & 3;
    const int bm   = blockIdx.y * 128;
    const int bn   = blockIdx.x * 128;

    float acc[4][4][4];
    #pragma unroll
    for (int i = 0; i < 4; i++)
        #pragma unroll
        for (int j = 0; j < 4; j++)
            #pragma unroll
            for (int q = 0; q < 4; q++) acc[i][j][q] = 0.f;

    const int nCh = K / 32;

#define LOAD_STAGE(IT, S) do {                                                \
    const float* Ab = A + (size_t)bm * K + (IT) * 32;                         \
    const float* Wb = W + (size_t)bn * K + (IT) * 32;                         \
    float* As_ = sg + (S) * (2 * TILE_F);                                     \
    float* Bs_ = As_ + TILE_F;                                                \
    _Pragma("unroll")                                                         \
    for (int p = 0; p < 4; p++) {                                             \
        const int idx = tid + p * 256;                                        \
        const int row = idx >> 3;                                             \
        const int c4  = (idx & 7) * 4;                                        \
        cp16(smem_u32(&As_[row * ASTR + c4]), &Ab[(size_t)row * K + c4]);     \
        cp16(smem_u32(&Bs_[row * ASTR + c4]), &Wb[(size_t)row * K + c4]);     \
    }                                                                         \
    asm volatile("cp.async.commit_group;" ::: "memory");                      \
} while (0)

    LOAD_STAGE(0, 0);

    for (int it = 0; it < nCh; it++) {
        const int s = it & 1;
        if (it + 1 < nCh) {
            LOAD_STAGE(it + 1, s ^ 1);
            asm volatile("cp.async.wait_group 1;" ::: "memory");
        } else {
            asm volatile("cp.async.wait_group 0;" ::: "memory");
        }
        __syncthreads();

        const float* As_ = sg + s * (2 * TILE_F);
        const float* Bs_ = As_ + TILE_F;

        #pragma unroll
        for (int half = 0; half < 2; half++) {
            uint4 bfr[4];
            #pragma unroll
            for (int nf = 0; nf < 4; nf++) {
                const int n = wn * 32 + nf * 8 + gq;
                bfr[nf] = *(const uint4*)&Bs_[n * ASTR + jq * 8 + half * 4];
            }
            #pragma unroll
            for (int mf = 0; mf < 4; mf++) {
                const int m = wm * 64 + mf * 16 + gq;
                uint4 a0 = *(const uint4*)&As_[m * ASTR + jq * 8 + half * 4];
                uint4 a1 = *(const uint4*)&As_[(m + 8) * ASTR + jq * 8 + half * 4];
                #pragma unroll
                for (int nf = 0; nf < 4; nf++) {
                    mma_tf32(acc[mf][nf], a0.x, a1.x, a0.y, a1.y, bfr[nf].x, bfr[nf].y);
                    mma_tf32(acc[mf][nf], a0.z, a1.z, a0.w, a1.w, bfr[nf].z, bfr[nf].w);
                }
            }
        }
        __syncthreads();
    }

    #pragma unroll
    for (int mf = 0; mf < 4; mf++) {
        const int r = bm + wm * 64 + mf * 16 + gq;
        #pragma unroll
        for (int nf = 0; nf < 4; nf++) {
            const int n0 = bn + wn * 32 + nf * 8 + 2 * jq;
            *(float2*)&C[(size_t)r * Np + n0]       = make_float2(acc[mf][nf][0], acc[mf][nf][1]);
            *(float2*)&C[(size_t)(r + 8) * Np + n0] = make_float2(acc[mf][nf][2], acc[mf][nf][3]);
        }
    }
#undef LOAD_STAGE
}

// ---------------- RoPE + head split (writes tf32-rounded Q/K/V) ----------------
__global__ __launch_bounds__(256) void rope_kernel(const float* __restrict__ qkv,
                                                   const float* __restrict__ coords,
                                                   float* __restrict__ Qo,
                                                   float* __restrict__ Ko,
                                                   float* __restrict__ Vo)
{
    const int m = blockIdx.x;
    const int b = m >> 11;
    const int n = m & 2047;
    const float c0 = coords[m * 2 + 0];
    const float c1 = coords[m * 2 + 1];
    const float* src = qkv + (size_t)m * (3 * Dd);

    for (int t = threadIdx.x; t < 3 * Dd; t += 256) {
        const int which = t / Dd;
        const int r     = t - which * Dd;
        const int h     = r >> 6;
        const int d     = r & 63;
        float val;
        if (which == 2) {
            val = src[t];
        } else {
            const int slice = d >> 5;
            const int dl    = d & 31;
            const int j     = dl & 15;
            const int isodd = dl >> 4;
            const float coord = slice ? c1 : c0;
            const float invf  = exp2f(-13.0f * (float)j * (1.0f / 16.0f));
            const float f  = coord * invf;
            const float cs = cosf(f);
            const float sn = sinf(f);
            const int   e  = which * Dd + h * 64 + slice * 32 + 2 * j;
            const float t1 = src[e];
            const float t2 = src[e + 1];
            val = isodd ? (t1 * sn + t2 * cs) : (t1 * cs - t2 * sn);
            if (which == 0) val *= 0.125f;
        }
        float* dst = (which == 0) ? Qo : ((which == 1) ? Ko : Vo);
        dst[((size_t)(b * Hh + h) * Nn + n) * DH + d] = rnd_tf32(val);
    }
}

// ---------------- mma.sync tf32 flash attention ----------------
// Bq=256, Bk=64. 8 warps; warp w owns 32 q-rows (blocks at w*32 and w*32+16).
// K/Vt B-fragments loaded once per (g,half,t) and applied to both m-blocks.
#define FSTR 68
__global__ __launch_bounds__(256, 1) void attn_mma(const float* __restrict__ Q,
                                                   const float* __restrict__ K,
                                                   const float* __restrict__ V,
                                                   float* __restrict__ AO)
{
    extern __shared__ __align__(16) uint32_t sa[];
    uint32_t* Qs = sa;                     // [256][FSTR]
    uint32_t* Ps = Qs + 256 * FSTR;        // [256][FSTR]
    uint32_t* Ks = Ps + 256 * FSTR;        // [64][FSTR]
    uint32_t* Vt = Ks + 64 * FSTR;         // [64][FSTR]  (d-major)

    const int tid  = threadIdx.x;
    const int lane = tid & 31;
    const int wid  = tid >> 5;
    const int gq   = lane >> 2;
    const int jq   = lane & 3;
    const int ma   = wid * 32;             // m-block 0
    const int mb   = ma + 16;              // m-block 1
    const int bh   = blockIdx.y;
    const int q0   = blockIdx.x * 256;
    const int b    = bh / Hh;
    const int h    = bh - b * Hh;

    const float* Qbh = Q + (size_t)bh * Nn * DH;
    const float* Kbh = K + (size_t)bh * Nn * DH;
    const float* Vbh = V + (size_t)bh * Nn * DH;

    // stage Q tile (256x64), raw copy (pre-rounded)
    #pragma unroll
    for (int p = 0; p < 16; p++) {
        const int idx = tid + p * 256;     // 0..4095
        const int row = idx >> 4;
        const int c4  = (idx & 15) * 4;
        *(uint4*)&Qs[row * FSTR + c4] = *(const uint4*)&Qbh[(size_t)(q0 + row) * DH + c4];
    }

    float o[2][8][4];
    float mx[2][2], ll[2][2];
    #pragma unroll
    for (int bkl = 0; bkl < 2; bkl++) {
        mx[bkl][0] = mx[bkl][1] = -1e30f;
        ll[bkl][0] = ll[bkl][1] = 0.f;
        #pragma unroll
        for (int t = 0; t < 8; t++)
            #pragma unroll
            for (int j = 0; j < 4; j++) o[bkl][t][j] = 0.f;
    }

    for (int k0 = 0; k0 < Nn; k0 += 64) {
        __syncthreads();
        // stage K tile (64x64) raw
        #pragma unroll
        for (int p = 0; p < 4; p++) {
            const int idx = tid + p * 256;
            const int row = idx >> 4;
            const int c4  = (idx & 15) * 4;
            *(uint4*)&Ks[row * FSTR + c4] = *(const uint4*)&Kbh[(size_t)(k0 + row) * DH + c4];
        }
        // stage V transposed: Vt[d][k] raw
        #pragma unroll
        for (int p = 0; p < 4; p++) {
            const int idx = tid + p * 256;
            const int kk  = idx & 63;
            const int d0  = (idx >> 6) * 4;
            uint4 vv = *(const uint4*)&Vbh[(size_t)(k0 + kk) * DH + d0];
            Vt[(d0 + 0) * FSTR + kk] = vv.x;
            Vt[(d0 + 1) * FSTR + kk] = vv.y;
            Vt[(d0 + 2) * FSTR + kk] = vv.z;
            Vt[(d0 + 3) * FSTR + kk] = vv.w;
        }
        __syncthreads();

        // ---- S = Q K^T for both m-blocks (B loaded once) ----
        float s0[8][4], s1[8][4];
        #pragma unroll
        for (int t = 0; t < 8; t++)
            #pragma unroll
            for (int j = 0; j < 4; j++) { s0[t][j] = 0.f; s1[t][j] = 0.f; }

        #pragma unroll
        for (int g = 0; g < 2; g++) {
            #pragma unroll
            for (int half = 0; half < 2; half++) {
                const int kc = g * 32 + half * 4 + jq * 8;
                uint4 a00 = *(const uint4*)&Qs[(ma + gq) * FSTR + kc];
                uint4 a01 = *(const uint4*)&Qs[(ma + gq + 8) * FSTR + kc];
                uint4 a10 = *(const uint4*)&Qs[(mb + gq) * FSTR + kc];
                uint4 a11 = *(const uint4*)&Qs[(mb + gq + 8) * FSTR + kc];
                #pragma unroll
                for (int t = 0; t < 8; t++) {
                    uint4 bv = *(const uint4*)&Ks[(t * 8 + gq) * FSTR + kc];
                    mma_tf32(s0[t], a00.x, a01.x, a00.y, a01.y, bv.x, bv.y);
                    mma_tf32(s0[t], a00.z, a01.z, a00.w, a01.w, bv.z, bv.w);
                    mma_tf32(s1[t], a10.x, a11.x, a10.y, a11.y, bv.x, bv.y);
                    mma_tf32(s1[t], a10.z, a11.z, a10.w, a11.w, bv.z, bv.w);
                }
            }
        }

        // ---- online softmax per m-block ----
        #pragma unroll
        for (int bkl = 0; bkl < 2; bkl++) {
            float (*s)[4] = bkl ? s1 : s0;
            const int mrow = bkl ? mb : ma;
            float smax_lo = -1e30f, smax_hi = -1e30f;
            #pragma unroll
            for (int t = 0; t < 8; t++) {
                smax_lo = fmaxf(smax_lo, fmaxf(s[t][0], s[t][1]));
                smax_hi = fmaxf(smax_hi, fmaxf(s[t][2], s[t][3]));
            }
            #pragma unroll
            for (int off = 1; off <= 2; off <<= 1) {
                smax_lo = fmaxf(smax_lo, __shfl_xor_sync(0xffffffffu, smax_lo, off));
                smax_hi = fmaxf(smax_hi, __shfl_xor_sync(0xffffffffu, smax_hi, off));
            }
            const float mn_lo = fmaxf(mx[bkl][0], smax_lo);
            const float mn_hi = fmaxf(mx[bkl][1], smax_hi);
            const float cr_lo = __expf(mx[bkl][0] - mn_lo);
            const float cr_hi = __expf(mx[bkl][1] - mn_hi);
            mx[bkl][0] = mn_lo; mx[bkl][1] = mn_hi;

            float ls_lo = 0.f, ls_hi = 0.f;
            #pragma unroll
            for (int t = 0; t < 8; t++) {
                float p0 = __expf(s[t][0] - mn_lo);
                float p1 = __expf(s[t][1] - mn_lo);
                float p2 = __expf(s[t][2] - mn_hi);
                float p3 = __expf(s[t][3] - mn_hi);
                ls_lo += p0 + p1;  ls_hi += p2 + p3;
                const int col = t * 8 + 2 * jq;
                Ps[(mrow + gq) * FSTR + col]         = cvt_tf32(p0);
                Ps[(mrow + gq) * FSTR + col + 1]     = cvt_tf32(p1);
                Ps[(mrow + gq + 8) * FSTR + col]     = cvt_tf32(p2);
                Ps[(mrow + gq + 8) * FSTR + col + 1] = cvt_tf32(p3);
            }
            #pragma unroll
            for (int off = 1; off <= 2; off <<= 1) {
                ls_lo += __shfl_xor_sync(0xffffffffu, ls_lo, off);
                ls_hi += __shfl_xor_sync(0xffffffffu, ls_hi, off);
            }
            ll[bkl][0] = ll[bkl][0] * cr_lo + ls_lo;
            ll[bkl][1] = ll[bkl][1] * cr_hi + ls_hi;
            #pragma unroll
            for (int t = 0; t < 8; t++) {
                o[bkl][t][0] *= cr_lo; o[bkl][t][1] *= cr_lo;
                o[bkl][t][2] *= cr_hi; o[bkl][t][3] *= cr_hi;
            }
        }
        __syncwarp();

        // ---- O += P V (B loaded once, both m-blocks) ----
        #pragma unroll
        for (int g = 0; g < 2; g++) {
            #pragma unroll
            for (int half = 0; half < 2; half++) {
                const int kc = g * 32 + half * 4 + jq * 8;
                uint4 a00 = *(const uint4*)&Ps[(ma + gq) * FSTR + kc];
                uint4 a01 = *(const uint4*)&Ps[(ma + gq + 8) * FSTR + kc];
                uint4 a10 = *(const uint4*)&Ps[(mb + gq) * FSTR + kc];
                uint4 a11 = *(const uint4*)&Ps[(mb + gq + 8) * FSTR + kc];
                #pragma unroll
                for (int t = 0; t < 8; t++) {
                    uint4 bv = *(const uint4*)&Vt[(t * 8 + gq) * FSTR + kc];
                    mma_tf32(o[0][t], a00.x, a01.x, a00.y, a01.y, bv.x, bv.y);
                    mma_tf32(o[0][t], a00.z, a01.z, a00.w, a01.w, bv.z, bv.w);
                    mma_tf32(o[1][t], a10.x, a11.x, a10.y, a11.y, bv.x, bv.y);
                    mma_tf32(o[1][t], a10.z, a11.z, a10.w, a11.w, bv.z, bv.w);
                }
            }
        }
    }

    // epilogue: normalize, round to tf32, write AO[b][n][h*64+d]
    #pragma unroll
    for (int bkl = 0; bkl < 2; bkl++) {
        const int mrow = bkl ? mb : ma;
        const float inv_lo = 1.0f / ll[bkl][0];
        const float inv_hi = 1.0f / ll[bkl][1];
        #pragma unroll
        for (int t = 0; t < 8; t++) {
            const int col = h * DH + t * 8 + 2 * jq;
            const size_t r0 = (size_t)(b * Nn + q0 + mrow + gq) * Dd + col;
            const size_t r1 = (size_t)(b * Nn + q0 + mrow + gq + 8) * Dd + col;
            *(float2*)&AO[r0] = make_float2(rnd_tf32(o[bkl][t][0] * inv_lo),
                                            rnd_tf32(o[bkl][t][1] * inv_lo));
            *(float2*)&AO[r1] = make_float2(rnd_tf32(o[bkl][t][2] * inv_hi),
                                            rnd_tf32(o[bkl][t][3] * inv_hi));
        }
    }
}

// ---------------- launch ----------------
extern "C" void kernel_launch(void* const* d_in, const int* in_sizes, int n_in,
                              void* d_out, int out_size)
{
    const float* x      = (const float*)d_in[0];
    const float* coords = (const float*)d_in[1];
    const float* gamma  = (const float*)d_in[2];
    const float* beta   = (const float*)d_in[3];
    const float* wqkv   = (const float*)d_in[4];
    const float* wout   = (const float*)d_in[5];
    float* out = (float*)d_out;

    float *xn, *qkv, *q, *k, *v, *ao, *wq, *wo;
    cudaGetSymbolAddress((void**)&xn,  g_xn);
    cudaGetSymbolAddress((void**)&qkv, g_qkv);
    cudaGetSymbolAddress((void**)&q,   g_q);
    cudaGetSymbolAddress((void**)&k,   g_k);
    cudaGetSymbolAddress((void**)&v,   g_v);
    cudaGetSymbolAddress((void**)&ao,  g_ao);
    cudaGetSymbolAddress((void**)&wq,  g_wq);
    cudaGetSymbolAddress((void**)&wo,  g_wo);

    const int gemm_smem = 2 * 2 * TILE_F * (int)sizeof(float);          // 73728 B
    const int attn_smem = (2 * 256 * FSTR + 2 * 64 * FSTR) * 4;         // 174080 B
    cudaFuncSetAttribute(gemm_mma, cudaFuncAttributeMaxDynamicSharedMemorySize, gemm_smem);
    cudaFuncSetAttribute(attn_mma, cudaFuncAttributeMaxDynamicSharedMemorySize, attn_smem);

    const int nwq = 3 * Dd * Dd, nwo = Dd * Dd;
    cvtw_kernel<<<nwq / 1024, 256>>>(wqkv, wq, nwq);
    cvtw_kernel<<<nwo / 1024, 256>>>(wout, wo, nwo);
    ln_kernel<<<M_TOT, 256>>>(x, gamma, beta, xn);
    gemm_mma<<<dim3(3 * Dd / 128, M_TOT / 128), 256, gemm_smem>>>(xn, wq, qkv, 3 * Dd, Dd);
    rope_kernel<<<M_TOT, 256>>>(qkv, coords, q, k, v);
    attn_mma<<<dim3(Nn / 256, BH), 256, attn_smem>>>(q, k, v, ao);
    gemm_mma<<<dim3(Dd / 128, M_TOT / 128), 256, gemm_smem>>>(ao, wo, out, Dd, Dd);
}